// round 14
// baseline (speedup 1.0000x reference)
#include <cuda_runtime.h>
#include <cuda_fp16.h>
#include <cstdint>
#include <cstddef>

#define DEVINL __device__ __forceinline__

// ---------------- problem constants ----------------
constexpr int Bn = 8, Sn = 2048, Hn = 1024, Pn = 320, Vn = 32000;
constexpr int Mrows = Bn * Pn;   // 2560
constexpr int Kdim = Hn;         // 1024

// M pipeline chunks
constexpr int MC0 = 512;                 // 4 M-tiles
constexpr int MC1 = Mrows - MC0;         // 2048 = 16 M-tiles

// ---------------- GEMM tiling ----------------
constexpr int MT = 128;
constexpr int NT = 128;
constexpr int KC = 64;                    // fp16 K per stage (128B per A row)
constexpr int NS = 3;
constexpr int NITERS = Kdim / KC;         // 16

constexpr int BPB = NT * 2 + 16;          // 272B B row pitch (conflict-free trans reads)
constexpr int STAGE_A = MT * KC * 2;      // 16384 B
constexpr int STAGE_B = KC * BPB;         // 17408 B
constexpr int STAGE_BYTES = STAGE_A + STAGE_B;   // 33792 B
constexpr int SMEM_TOTAL = NS * STAGE_BYTES;     // 101376 B -> 2 CTAs/SM

// ---------------- scratch (device globals) ----------------
__device__ __align__(1024) __half g_W2h[(size_t)Kdim * Vn];   // 65 MB
__device__ __align__(1024) __half g_W1h[(size_t)Kdim * Hn];   // 2 MB
__device__ __align__(1024) __half g_Xg[(size_t)Mrows * Kdim]; // 5.2 MB
__device__ __align__(1024) float  g_Hb[(size_t)Mrows * Kdim]; // 10.5 MB
__device__ __align__(1024) __half g_Ha[(size_t)Mrows * Kdim]; // 5.2 MB

// ---------------- PTX helpers (compute_103-safe) ----------------
DEVINL uint32_t smem_u32(const void* p) {
    uint32_t a;
    asm("{ .reg .u64 t; cvta.to.shared.u64 t, %1; cvt.u32.u64 %0, t; }" : "=r"(a) : "l"(p));
    return a;
}
DEVINL void cp16(uint32_t dst, const void* src) {
    asm volatile("cp.async.cg.shared.global [%0], [%1], 16;" :: "r"(dst), "l"(src) : "memory");
}
DEVINL void cp_commit() { asm volatile("cp.async.commit_group;" ::: "memory"); }
DEVINL void ldsm4(uint32_t& r0, uint32_t& r1, uint32_t& r2, uint32_t& r3, uint32_t a) {
    asm volatile("ldmatrix.sync.aligned.m8n8.x4.shared.b16 {%0,%1,%2,%3}, [%4];"
                 : "=r"(r0), "=r"(r1), "=r"(r2), "=r"(r3) : "r"(a));
}
DEVINL void ldsm4t(uint32_t& r0, uint32_t& r1, uint32_t& r2, uint32_t& r3, uint32_t a) {
    asm volatile("ldmatrix.sync.aligned.m8n8.x4.trans.shared.b16 {%0,%1,%2,%3}, [%4];"
                 : "=r"(r0), "=r"(r1), "=r"(r2), "=r"(r3) : "r"(a));
}
DEVINL void mma_f16(float& c0, float& c1, float& c2, float& c3,
                    uint32_t a0, uint32_t a1, uint32_t a2, uint32_t a3,
                    uint32_t b0, uint32_t b1) {
    asm volatile(
        "mma.sync.aligned.m16n8k16.row.col.f32.f16.f16.f32 "
        "{%0,%1,%2,%3}, {%4,%5,%6,%7}, {%8,%9}, {%0,%1,%2,%3};"
        : "+f"(c0), "+f"(c1), "+f"(c2), "+f"(c3)
        : "r"(a0), "r"(a1), "r"(a2), "r"(a3), "r"(b0), "r"(b1));
}

// ---------------- stage loader: one of 4 parts (2 cp16/thread per part) ----------------
DEVINL void issue_stage_part(uint32_t sb, const char* Ab, const char* Bb, size_t ldb2,
                             int it, int s, int tid, int part) {
    uint32_t sa = sb + s * STAGE_BYTES;
    uint32_t sB = sa + STAGE_A;
    const char* ga = Ab + (size_t)it * (KC * 2);
    const char* gb = Bb + (size_t)it * KC * ldb2;
    {   // A chunk 'part'
        int idx = tid + part * 256;
        int row = idx >> 3, ch = idx & 7;
        cp16(sa + row * 128 + ((ch * 16) ^ ((row & 7) << 4)),
             ga + (size_t)row * (Kdim * 2) + ch * 16);
    }
    {   // B chunk 'part'
        int idx = tid + part * 256;
        int row = idx >> 4, ch = idx & 15;
        cp16(sB + row * BPB + ch * 16, gb + (size_t)row * ldb2 + ch * 16);
    }
}
DEVINL void issue_stage(uint32_t sb, const char* Ab, const char* Bb, size_t ldb2,
                        int it, int s, int tid) {
#pragma unroll
    for (int p = 0; p < 4; p++) issue_stage_part(sb, Ab, Bb, ldb2, it, s, tid, p);
}

// ---------------- FP16 mma.sync GEMM: C = A @ B + bias (opt ReLU) ----------------
// 8 warps: 2 (M) x 4 (N); warp tile 64x32; m16n8k16. B fragments double-buffered.
// cp.async for the next stage is issued in 4 parts interleaved with the 4 k-steps;
// A fragments are loaded BEFORE the cp part so MMA operands never queue behind it.
__global__ void __launch_bounds__(256, 2) gemm_f16_kernel(
    const __half* __restrict__ A, const __half* __restrict__ Bmat,
    const float* __restrict__ bias, float* __restrict__ C,
    long long ldb, long long ldc, int do_relu)
{
    extern __shared__ __align__(1024) char smem[];
    uint32_t sb = smem_u32(smem);
    const int tid = threadIdx.x, wid = tid >> 5, lane = tid & 31;
    const int wm = wid & 1, wn = wid >> 1;
    const long long m0 = (long long)blockIdx.x * MT;
    const long long n0 = (long long)blockIdx.y * NT;

    const char* Ab = (const char*)(A + (size_t)m0 * Kdim);
    const char* Bb = (const char*)(Bmat + n0);
    const size_t ldb2 = (size_t)ldb * 2;

    // A ldmatrix addressing (K-major, swizzled)
    const int sub = lane >> 3, r8 = lane & 7;
    const uint32_t kxor = (uint32_t)(r8 << 4);
    uint32_t aoff[4];
#pragma unroll
    for (int mt = 0; mt < 4; mt++)
        aoff[mt] = (uint32_t)((wm * 64 + mt * 16 + (sub & 1) * 8 + r8) * 128);
    const uint32_t akseg = (uint32_t)((sub >> 1) * 16);

    // B ldmatrix.trans addressing ([K][N] smem, pitch 272B)
    const uint32_t bkrow = (uint32_t)(((sub & 1) * 8 + r8) * BPB);
    uint32_t bnoff[2];
#pragma unroll
    for (int p = 0; p < 2; p++)
        bnoff[p] = (uint32_t)((wn * 32 + p * 16 + (sub >> 1) * 8) * 2);

    float acc[4][4][4];
#pragma unroll
    for (int i = 0; i < 4; i++)
#pragma unroll
        for (int j = 0; j < 4; j++)
#pragma unroll
            for (int r = 0; r < 4; r++) acc[i][j][r] = 0.f;

#pragma unroll
    for (int j = 0; j < NS - 1; j++) { issue_stage(sb, Ab, Bb, ldb2, j, j, tid); cp_commit(); }

    for (int it = 0; it < NITERS; ++it) {
        asm volatile("cp.async.wait_group %0;" :: "n"(NS - 2) : "memory");
        __syncthreads();

        uint32_t sa = sb + (it % NS) * STAGE_BYTES;
        uint32_t sB = sa + STAGE_A;
        const int jn = it + NS - 1;
        const bool pref = jn < NITERS;
        const int js = jn % NS;

        // B fragment double buffer: prefetch ks=0 fragments first
        uint32_t b[2][4][2];
#pragma unroll
        for (int p = 0; p < 2; p++) {
            uint32_t r0, r1, r2, r3;
            ldsm4t(r0, r1, r2, r3, sB + bkrow + bnoff[p]);
            b[0][2 * p][0] = r0;     b[0][2 * p][1] = r1;
            b[0][2 * p + 1][0] = r2; b[0][2 * p + 1][1] = r3;
        }

#pragma unroll
        for (int ks = 0; ks < KC / 16; ks++) {
            const int cur = ks & 1, nxt = cur ^ 1;
            // A fragments for this k-step first (MMA operand path)
            uint32_t a[4][4];
#pragma unroll
            for (int mt = 0; mt < 4; mt++)
                ldsm4(a[mt][0], a[mt][1], a[mt][2], a[mt][3],
                      sa + aoff[mt] + (((uint32_t)(ks * 32) + akseg) ^ kxor));
            // then the next-stage cp.async part
            if (pref) issue_stage_part(sb, Ab, Bb, ldb2, jn, js, tid, ks);
            // B fragments for the next k-step
            if (ks < KC / 16 - 1) {
#pragma unroll
                for (int p = 0; p < 2; p++) {
                    uint32_t r0, r1, r2, r3;
                    ldsm4t(r0, r1, r2, r3,
                           sB + (uint32_t)((ks + 1) * 16) * BPB + bkrow + bnoff[p]);
                    b[nxt][2 * p][0] = r0;     b[nxt][2 * p][1] = r1;
                    b[nxt][2 * p + 1][0] = r2; b[nxt][2 * p + 1][1] = r3;
                }
            }
#pragma unroll
            for (int mt = 0; mt < 4; mt++)
#pragma unroll
                for (int nt = 0; nt < 4; nt++)
                    mma_f16(acc[mt][nt][0], acc[mt][nt][1], acc[mt][nt][2], acc[mt][nt][3],
                            a[mt][0], a[mt][1], a[mt][2], a[mt][3],
                            b[cur][nt][0], b[cur][nt][1]);
        }
        cp_commit();   // one group per iteration keeps accounting uniform
    }

    // ---------------- epilogue ----------------
    const int crow = lane >> 2, ccol2 = (lane & 3) * 2;
#pragma unroll
    for (int mt = 0; mt < 4; mt++) {
        long long r = m0 + wm * 64 + mt * 16 + crow;
#pragma unroll
        for (int nt = 0; nt < 4; nt++) {
            long long cc = n0 + wn * 32 + nt * 8 + ccol2;
            float2 bv = *reinterpret_cast<const float2*>(bias + cc);
            float2 o0, o1;
            o0.x = acc[mt][nt][0] + bv.x; o0.y = acc[mt][nt][1] + bv.y;
            o1.x = acc[mt][nt][2] + bv.x; o1.y = acc[mt][nt][3] + bv.y;
            if (do_relu) {
                o0.x = fmaxf(o0.x, 0.f); o0.y = fmaxf(o0.y, 0.f);
                o1.x = fmaxf(o1.x, 0.f); o1.y = fmaxf(o1.y, 0.f);
            }
            *reinterpret_cast<float2*>(C + (size_t)r * ldc + cc) = o0;
            *reinterpret_cast<float2*>(C + (size_t)(r + 8) * ldc + cc) = o1;
        }
    }
}

// ---------------- fp32 -> fp16 convert, 4 independent chains per iteration (MLP=4) ----------
__global__ void convert_kernel(const float4* __restrict__ in, uint2* __restrict__ out, int n4) {
    const int nt = blockDim.x;                       // 256
    int base = (blockIdx.x * nt) * 4 + threadIdx.x;
    const int stride = gridDim.x * nt * 4;
    for (; base < n4; base += stride) {
        float4 v[4];
        int idx[4];
        bool ok[4];
#pragma unroll
        for (int j = 0; j < 4; j++) {
            idx[j] = base + j * nt;
            ok[j] = idx[j] < n4;
            if (ok[j]) v[j] = in[idx[j]];
        }
#pragma unroll
        for (int j = 0; j < 4; j++) {
            if (ok[j]) {
                __half2 lo = __floats2half2_rn(v[j].x, v[j].y);
                __half2 hi = __floats2half2_rn(v[j].z, v[j].w);
                uint2 o;
                o.x = *reinterpret_cast<uint32_t*>(&lo);
                o.y = *reinterpret_cast<uint32_t*>(&hi);
                out[idx[j]] = o;
            }
        }
    }
}

// ---------------- gather with fused int64/int32 width probe; 4 rows/block, MLP=4 ----------------
__global__ void gather_kernel(const float* __restrict__ X, const void* __restrict__ pp) {
    __shared__ int flag;
    int tid = threadIdx.x;
    if (tid == 0) flag = 0;
    __syncthreads();
    if (tid < 64) {
        unsigned long long v = ((const unsigned long long*)pp)[tid];
        if (v >= (1ull << 32)) atomicOr(&flag, 1);
    }
    __syncthreads();
    const bool p64 = (flag == 0);

    const int rbase = blockIdx.x * 4;
    const int rl = tid >> 6;
    const int cl = tid & 63;
    const int i = rbase + rl;
    const int b = i / Pn;
    long long pos = p64 ? ((const long long*)pp)[i]
                        : (long long)((const int*)pp)[i];
    const float4* src = (const float4*)(X + ((size_t)b * Sn + (size_t)pos) * Hn);
    uint2* dst = (uint2*)(g_Xg + (size_t)i * Hn);
#pragma unroll
    for (int j = 0; j < 4; j++) {
        int c = cl + j * 64;
        float4 v = src[c];
        __half2 lo = __floats2half2_rn(v.x, v.y);
        __half2 hi = __floats2half2_rn(v.z, v.w);
        uint2 o;
        o.x = *reinterpret_cast<uint32_t*>(&lo);
        o.y = *reinterpret_cast<uint32_t*>(&hi);
        dst[c] = o;
    }
}

// ---------------- rowwise LayerNorm: g_Hb (fp32) -> g_Ha (fp16), row range offset ----------------
__global__ void ln_kernel(const float* __restrict__ gamma, const float* __restrict__ beta, int row0) {
    int row = row0 + blockIdx.x, tid = threadIdx.x;
    const float4* rp = (const float4*)(g_Hb + (size_t)row * Hn);
    float4 v = rp[tid];
    float s = v.x + v.y + v.z + v.w;
    float q = v.x * v.x + v.y * v.y + v.z * v.z + v.w * v.w;
#pragma unroll
    for (int o = 16; o; o >>= 1) {
        s += __shfl_xor_sync(0xFFFFFFFFu, s, o);
        q += __shfl_xor_sync(0xFFFFFFFFu, q, o);
    }
    __shared__ float ss[8], sq[8];
    __shared__ float smu, sinv;
    int wid = tid >> 5, lid = tid & 31;
    if (lid == 0) { ss[wid] = s; sq[wid] = q; }
    __syncthreads();
    if (tid == 0) {
        float ts = 0.f, tq = 0.f;
#pragma unroll
        for (int w = 0; w < 8; w++) { ts += ss[w]; tq += sq[w]; }
        float mu = ts / Hn;
        float var = tq / Hn - mu * mu;
        smu = mu; sinv = rsqrtf(var + 1e-5f);
    }
    __syncthreads();
    float mu = smu, inv = sinv;
    float4 gv = ((const float4*)gamma)[tid];
    float4 bv = ((const float4*)beta)[tid];
    float o0 = (v.x - mu) * inv * gv.x + bv.x;
    float o1 = (v.y - mu) * inv * gv.y + bv.y;
    float o2 = (v.z - mu) * inv * gv.z + bv.z;
    float o3 = (v.w - mu) * inv * gv.w + bv.w;
    __half2 lo = __floats2half2_rn(o0, o1);
    __half2 hi = __floats2half2_rn(o2, o3);
    uint2 o;
    o.x = *reinterpret_cast<uint32_t*>(&lo);
    o.y = *reinterpret_cast<uint32_t*>(&hi);
    ((uint2*)(g_Ha + (size_t)row * Hn))[tid] = o;
}

// ---------------- launch (R9/R13 winning schedule) ----------------
extern "C" void kernel_launch(void* const* d_in, const int* in_sizes, int n_in,
                              void* d_out, int out_size) {
    const float* X     = (const float*)d_in[0];
    const void*  pos   = d_in[1];
    const float* W1    = (const float*)d_in[2];
    const float* b1    = (const float*)d_in[3];
    const float* gamma = (const float*)d_in[4];
    const float* beta  = (const float*)d_in[5];
    const float* W2    = (const float*)d_in[6];
    const float* b2    = (const float*)d_in[7];
    float* out = (float*)d_out;

    cudaFuncSetAttribute(gemm_f16_kernel, cudaFuncAttributeMaxDynamicSharedMemorySize, SMEM_TOTAL);

    void *pW1h, *pW2h, *pXg, *pHb, *pHa;
    cudaGetSymbolAddress(&pW1h, g_W1h);
    cudaGetSymbolAddress(&pW2h, g_W2h);
    cudaGetSymbolAddress(&pXg, g_Xg);
    cudaGetSymbolAddress(&pHb, g_Hb);
    cudaGetSymbolAddress(&pHa, g_Ha);
    const __half* Xg = (const __half*)pXg;
    float* Hb = (float*)pHb;
    const __half* Ha = (const __half*)pHa;

    static cudaStream_t sW = nullptr, sW1 = nullptr, sFE = nullptr;
    static cudaEvent_t eFork = nullptr, eJoin = nullptr, eJoin1 = nullptr,
                       eG = nullptr, eC1 = nullptr;
    if (!sW) {
        cudaStreamCreateWithFlags(&sW, cudaStreamNonBlocking);
        cudaStreamCreateWithFlags(&sW1, cudaStreamNonBlocking);
        cudaStreamCreateWithFlags(&sFE, cudaStreamNonBlocking);
        cudaEventCreateWithFlags(&eFork, cudaEventDisableTiming);
        cudaEventCreateWithFlags(&eJoin, cudaEventDisableTiming);
        cudaEventCreateWithFlags(&eJoin1, cudaEventDisableTiming);
        cudaEventCreateWithFlags(&eG, cudaEventDisableTiming);
        cudaEventCreateWithFlags(&eC1, cudaEventDisableTiming);
    }

    // Fork: weight converts overlap with the front-end.
    cudaEventRecord(eFork, 0);
    cudaStreamWaitEvent(sW, eFork, 0);
    convert_kernel<<<1024, 256, 0, sW>>>((const float4*)W2, (uint2*)pW2h, Kdim * Vn / 4);
    cudaEventRecord(eJoin, sW);
    cudaStreamWaitEvent(sW1, eFork, 0);
    convert_kernel<<<256, 256, 0, sW1>>>((const float4*)W1, (uint2*)pW1h, Kdim * Hn / 4);
    cudaEventRecord(eJoin1, sW1);

    // Main stream: gather (width probe fused).
    gather_kernel<<<Mrows / 4, 256>>>(X, pos);
    cudaEventRecord(eG, 0);

    // ---- chunk c0 front-end (rows [0, MC0)) on main ----
    cudaStreamWaitEvent(0, eJoin1, 0);
    gemm_f16_kernel<<<dim3(MC0 / MT, Hn / NT), 256, SMEM_TOTAL>>>(
        Xg, (const __half*)pW1h, b1, Hb, (long long)Hn, (long long)Hn, 1);
    ln_kernel<<<MC0, 256>>>(gamma, beta, 0);

    // ---- chunk c1 front-end + GEMM2(c1) on sFE (independent of GEMM2(c0)) ----
    cudaStreamWaitEvent(sFE, eG, 0);
    cudaStreamWaitEvent(sFE, eJoin1, 0);
    gemm_f16_kernel<<<dim3(MC1 / MT, Hn / NT), 256, SMEM_TOTAL, sFE>>>(
        Xg + (size_t)MC0 * Kdim, (const __half*)pW1h, b1, Hb + (size_t)MC0 * Hn,
        (long long)Hn, (long long)Hn, 1);
    ln_kernel<<<MC1, 256, 0, sFE>>>(gamma, beta, MC0);
    cudaStreamWaitEvent(sFE, eJoin, 0);
    gemm_f16_kernel<<<dim3(MC1 / MT, Vn / NT), 256, SMEM_TOTAL, sFE>>>(
        Ha + (size_t)MC0 * Kdim, (const __half*)pW2h, b2, out + (size_t)MC0 * Vn,
        (long long)Vn, (long long)Vn, 0);
    cudaEventRecord(eC1, sFE);

    // ---- GEMM2(c0) on main, concurrent with GEMM2(c1) ----
    cudaStreamWaitEvent(0, eJoin, 0);
    gemm_f16_kernel<<<dim3(MC0 / MT, Vn / NT), 256, SMEM_TOTAL>>>(
        Ha, (const __half*)pW2h, b2, out, (long long)Vn, (long long)Vn, 0);

    // join the side branch back into the capture-origin stream
    cudaStreamWaitEvent(0, eC1, 0);
}

// round 15
// speedup vs baseline: 1.0258x; 1.0258x over previous
#include <cuda_runtime.h>
#include <cuda_fp16.h>
#include <cstdint>
#include <cstddef>

#define DEVINL __device__ __forceinline__

// ---------------- problem constants ----------------
constexpr int Bn = 8, Sn = 2048, Hn = 1024, Pn = 320, Vn = 32000;
constexpr int Mrows = Bn * Pn;   // 2560
constexpr int Kdim = Hn;         // 1024

// M pipeline chunks
constexpr int MC0 = 512;                 // 4 M-tiles
constexpr int MC1 = Mrows - MC0;         // 2048 = 16 M-tiles

// ---------------- GEMM tiling ----------------
constexpr int MT = 128;
constexpr int NT = 128;
constexpr int KC = 64;                    // fp16 K per stage (128B per A row)
constexpr int NS = 3;
constexpr int NITERS = Kdim / KC;         // 16

constexpr int BPB = NT * 2 + 16;          // 272B B row pitch (conflict-free trans reads)
constexpr int STAGE_A = MT * KC * 2;      // 16384 B
constexpr int STAGE_B = KC * BPB;         // 17408 B
constexpr int STAGE_BYTES = STAGE_A + STAGE_B;   // 33792 B
constexpr int SMEM_TOTAL = NS * STAGE_BYTES;     // 101376 B -> 2 CTAs/SM

// ---------------- scratch (device globals) ----------------
__device__ __align__(1024) __half g_W2h[(size_t)Kdim * Vn];   // 65 MB
__device__ __align__(1024) __half g_W1h[(size_t)Kdim * Hn];   // 2 MB
__device__ __align__(1024) __half g_Xg[(size_t)Mrows * Kdim]; // 5.2 MB
__device__ __align__(1024) float  g_Hb[(size_t)Mrows * Kdim]; // 10.5 MB
__device__ __align__(1024) __half g_Ha[(size_t)Mrows * Kdim]; // 5.2 MB

// ---------------- PTX helpers (compute_103-safe) ----------------
DEVINL uint32_t smem_u32(const void* p) {
    uint32_t a;
    asm("{ .reg .u64 t; cvta.to.shared.u64 t, %1; cvt.u32.u64 %0, t; }" : "=r"(a) : "l"(p));
    return a;
}
DEVINL void cp16(uint32_t dst, const void* src) {
    asm volatile("cp.async.cg.shared.global [%0], [%1], 16;" :: "r"(dst), "l"(src) : "memory");
}
DEVINL void cp_commit() { asm volatile("cp.async.commit_group;" ::: "memory"); }
DEVINL void ldsm4(uint32_t& r0, uint32_t& r1, uint32_t& r2, uint32_t& r3, uint32_t a) {
    asm volatile("ldmatrix.sync.aligned.m8n8.x4.shared.b16 {%0,%1,%2,%3}, [%4];"
                 : "=r"(r0), "=r"(r1), "=r"(r2), "=r"(r3) : "r"(a));
}
DEVINL void ldsm4t(uint32_t& r0, uint32_t& r1, uint32_t& r2, uint32_t& r3, uint32_t a) {
    asm volatile("ldmatrix.sync.aligned.m8n8.x4.trans.shared.b16 {%0,%1,%2,%3}, [%4];"
                 : "=r"(r0), "=r"(r1), "=r"(r2), "=r"(r3) : "r"(a));
}
DEVINL void mma_f16(float& c0, float& c1, float& c2, float& c3,
                    uint32_t a0, uint32_t a1, uint32_t a2, uint32_t a3,
                    uint32_t b0, uint32_t b1) {
    asm volatile(
        "mma.sync.aligned.m16n8k16.row.col.f32.f16.f16.f32 "
        "{%0,%1,%2,%3}, {%4,%5,%6,%7}, {%8,%9}, {%0,%1,%2,%3};"
        : "+f"(c0), "+f"(c1), "+f"(c2), "+f"(c3)
        : "r"(a0), "r"(a1), "r"(a2), "r"(a3), "r"(b0), "r"(b1));
}

// ---------------- stage loader: one of 4 parts (2 cp16/thread per part) ----------------
DEVINL void issue_stage_part(uint32_t sb, const char* Ab, const char* Bb, size_t ldb2,
                             int it, int s, int tid, int part) {
    uint32_t sa = sb + s * STAGE_BYTES;
    uint32_t sB = sa + STAGE_A;
    const char* ga = Ab + (size_t)it * (KC * 2);
    const char* gb = Bb + (size_t)it * KC * ldb2;
    {   // A chunk 'part'
        int idx = tid + part * 256;
        int row = idx >> 3, ch = idx & 7;
        cp16(sa + row * 128 + ((ch * 16) ^ ((row & 7) << 4)),
             ga + (size_t)row * (Kdim * 2) + ch * 16);
    }
    {   // B chunk 'part'
        int idx = tid + part * 256;
        int row = idx >> 4, ch = idx & 15;
        cp16(sB + row * BPB + ch * 16, gb + (size_t)row * ldb2 + ch * 16);
    }
}
DEVINL void issue_stage(uint32_t sb, const char* Ab, const char* Bb, size_t ldb2,
                        int it, int s, int tid) {
#pragma unroll
    for (int p = 0; p < 4; p++) issue_stage_part(sb, Ab, Bb, ldb2, it, s, tid, p);
}

// ---------------- FP16 mma.sync GEMM: C = A @ B + bias (opt ReLU) ----------------
// EXACT R13 mainloop (478.0us): cp part issued between B-frag prefetch and A ldsm.
__global__ void __launch_bounds__(256, 2) gemm_f16_kernel(
    const __half* __restrict__ A, const __half* __restrict__ Bmat,
    const float* __restrict__ bias, float* __restrict__ C,
    long long ldb, long long ldc, int do_relu)
{
    extern __shared__ __align__(1024) char smem[];
    uint32_t sb = smem_u32(smem);
    const int tid = threadIdx.x, wid = tid >> 5, lane = tid & 31;
    const int wm = wid & 1, wn = wid >> 1;
    const long long m0 = (long long)blockIdx.x * MT;
    const long long n0 = (long long)blockIdx.y * NT;

    const char* Ab = (const char*)(A + (size_t)m0 * Kdim);
    const char* Bb = (const char*)(Bmat + n0);
    const size_t ldb2 = (size_t)ldb * 2;

    // A ldmatrix addressing (K-major, swizzled)
    const int sub = lane >> 3, r8 = lane & 7;
    const uint32_t kxor = (uint32_t)(r8 << 4);
    uint32_t aoff[4];
#pragma unroll
    for (int mt = 0; mt < 4; mt++)
        aoff[mt] = (uint32_t)((wm * 64 + mt * 16 + (sub & 1) * 8 + r8) * 128);
    const uint32_t akseg = (uint32_t)((sub >> 1) * 16);

    // B ldmatrix.trans addressing ([K][N] smem, pitch 272B)
    const uint32_t bkrow = (uint32_t)(((sub & 1) * 8 + r8) * BPB);
    uint32_t bnoff[2];
#pragma unroll
    for (int p = 0; p < 2; p++)
        bnoff[p] = (uint32_t)((wn * 32 + p * 16 + (sub >> 1) * 8) * 2);

    float acc[4][4][4];
#pragma unroll
    for (int i = 0; i < 4; i++)
#pragma unroll
        for (int j = 0; j < 4; j++)
#pragma unroll
            for (int r = 0; r < 4; r++) acc[i][j][r] = 0.f;

#pragma unroll
    for (int j = 0; j < NS - 1; j++) { issue_stage(sb, Ab, Bb, ldb2, j, j, tid); cp_commit(); }

    for (int it = 0; it < NITERS; ++it) {
        asm volatile("cp.async.wait_group %0;" :: "n"(NS - 2) : "memory");
        __syncthreads();

        uint32_t sa = sb + (it % NS) * STAGE_BYTES;
        uint32_t sB = sa + STAGE_A;
        const int jn = it + NS - 1;
        const bool pref = jn < NITERS;
        const int js = jn % NS;

        // B fragment double buffer: prefetch ks=0 fragments first
        uint32_t b[2][4][2];
#pragma unroll
        for (int p = 0; p < 2; p++) {
            uint32_t r0, r1, r2, r3;
            ldsm4t(r0, r1, r2, r3, sB + bkrow + bnoff[p]);
            b[0][2 * p][0] = r0;     b[0][2 * p][1] = r1;
            b[0][2 * p + 1][0] = r2; b[0][2 * p + 1][1] = r3;
        }

#pragma unroll
        for (int ks = 0; ks < KC / 16; ks++) {
            const int cur = ks & 1, nxt = cur ^ 1;
            if (pref) issue_stage_part(sb, Ab, Bb, ldb2, jn, js, tid, ks);
            if (ks < KC / 16 - 1) {
#pragma unroll
                for (int p = 0; p < 2; p++) {
                    uint32_t r0, r1, r2, r3;
                    ldsm4t(r0, r1, r2, r3,
                           sB + (uint32_t)((ks + 1) * 16) * BPB + bkrow + bnoff[p]);
                    b[nxt][2 * p][0] = r0;     b[nxt][2 * p][1] = r1;
                    b[nxt][2 * p + 1][0] = r2; b[nxt][2 * p + 1][1] = r3;
                }
            }
            uint32_t a[4][4];
#pragma unroll
            for (int mt = 0; mt < 4; mt++)
                ldsm4(a[mt][0], a[mt][1], a[mt][2], a[mt][3],
                      sa + aoff[mt] + (((uint32_t)(ks * 32) + akseg) ^ kxor));
#pragma unroll
            for (int mt = 0; mt < 4; mt++)
#pragma unroll
                for (int nt = 0; nt < 4; nt++)
                    mma_f16(acc[mt][nt][0], acc[mt][nt][1], acc[mt][nt][2], acc[mt][nt][3],
                            a[mt][0], a[mt][1], a[mt][2], a[mt][3],
                            b[cur][nt][0], b[cur][nt][1]);
        }
        cp_commit();   // one group per iteration (empty when !pref) keeps accounting uniform
    }

    // ---------------- epilogue ----------------
    const int crow = lane >> 2, ccol2 = (lane & 3) * 2;
#pragma unroll
    for (int mt = 0; mt < 4; mt++) {
        long long r = m0 + wm * 64 + mt * 16 + crow;
#pragma unroll
        for (int nt = 0; nt < 4; nt++) {
            long long cc = n0 + wn * 32 + nt * 8 + ccol2;
            float2 bv = *reinterpret_cast<const float2*>(bias + cc);
            float2 o0, o1;
            o0.x = acc[mt][nt][0] + bv.x; o0.y = acc[mt][nt][1] + bv.y;
            o1.x = acc[mt][nt][2] + bv.x; o1.y = acc[mt][nt][3] + bv.y;
            if (do_relu) {
                o0.x = fmaxf(o0.x, 0.f); o0.y = fmaxf(o0.y, 0.f);
                o1.x = fmaxf(o1.x, 0.f); o1.y = fmaxf(o1.y, 0.f);
            }
            *reinterpret_cast<float2*>(C + (size_t)r * ldc + cc) = o0;
            *reinterpret_cast<float2*>(C + (size_t)(r + 8) * ldc + cc) = o1;
        }
    }
}

// ---------------- fp32 -> fp16 convert, 4 chains/thread, NO predication ----------------
// Caller guarantees n4 % (gridDim.x * blockDim.x * 4) == 0.
__global__ void convert_kernel(const float4* __restrict__ in, uint2* __restrict__ out, int n4) {
    const int nt = blockDim.x;                       // 256
    int base = (blockIdx.x * nt) * 4 + threadIdx.x;
    const int stride = gridDim.x * nt * 4;
    for (; base < n4; base += stride) {
        float4 v[4];
#pragma unroll
        for (int j = 0; j < 4; j++) v[j] = in[base + j * nt];
#pragma unroll
        for (int j = 0; j < 4; j++) {
            __half2 lo = __floats2half2_rn(v[j].x, v[j].y);
            __half2 hi = __floats2half2_rn(v[j].z, v[j].w);
            uint2 o;
            o.x = *reinterpret_cast<uint32_t*>(&lo);
            o.y = *reinterpret_cast<uint32_t*>(&hi);
            out[base + j * nt] = o;
        }
    }
}

// ---------------- gather with fused int64/int32 width probe; 4 rows/block, MLP=4 ----------------
__global__ void gather_kernel(const float* __restrict__ X, const void* __restrict__ pp) {
    __shared__ int flag;
    int tid = threadIdx.x;
    if (tid == 0) flag = 0;
    __syncthreads();
    if (tid < 64) {
        unsigned long long v = ((const unsigned long long*)pp)[tid];
        if (v >= (1ull << 32)) atomicOr(&flag, 1);
    }
    __syncthreads();
    const bool p64 = (flag == 0);

    const int rbase = blockIdx.x * 4;
    const int rl = tid >> 6;
    const int cl = tid & 63;
    const int i = rbase + rl;
    const int b = i / Pn;
    long long pos = p64 ? ((const long long*)pp)[i]
                        : (long long)((const int*)pp)[i];
    const float4* src = (const float4*)(X + ((size_t)b * Sn + (size_t)pos) * Hn);
    uint2* dst = (uint2*)(g_Xg + (size_t)i * Hn);
#pragma unroll
    for (int j = 0; j < 4; j++) {
        int c = cl + j * 64;
        float4 v = src[c];
        __half2 lo = __floats2half2_rn(v.x, v.y);
        __half2 hi = __floats2half2_rn(v.z, v.w);
        uint2 o;
        o.x = *reinterpret_cast<uint32_t*>(&lo);
        o.y = *reinterpret_cast<uint32_t*>(&hi);
        dst[c] = o;
    }
}

// ---------------- rowwise LayerNorm: g_Hb (fp32) -> g_Ha (fp16), row range offset ----------------
__global__ void ln_kernel(const float* __restrict__ gamma, const float* __restrict__ beta, int row0) {
    int row = row0 + blockIdx.x, tid = threadIdx.x;
    const float4* rp = (const float4*)(g_Hb + (size_t)row * Hn);
    float4 v = rp[tid];
    float s = v.x + v.y + v.z + v.w;
    float q = v.x * v.x + v.y * v.y + v.z * v.z + v.w * v.w;
#pragma unroll
    for (int o = 16; o; o >>= 1) {
        s += __shfl_xor_sync(0xFFFFFFFFu, s, o);
        q += __shfl_xor_sync(0xFFFFFFFFu, q, o);
    }
    __shared__ float ss[8], sq[8];
    __shared__ float smu, sinv;
    int wid = tid >> 5, lid = tid & 31;
    if (lid == 0) { ss[wid] = s; sq[wid] = q; }
    __syncthreads();
    if (tid == 0) {
        float ts = 0.f, tq = 0.f;
#pragma unroll
        for (int w = 0; w < 8; w++) { ts += ss[w]; tq += sq[w]; }
        float mu = ts / Hn;
        float var = tq / Hn - mu * mu;
        smu = mu; sinv = rsqrtf(var + 1e-5f);
    }
    __syncthreads();
    float mu = smu, inv = sinv;
    float4 gv = ((const float4*)gamma)[tid];
    float4 bv = ((const float4*)beta)[tid];
    float o0 = (v.x - mu) * inv * gv.x + bv.x;
    float o1 = (v.y - mu) * inv * gv.y + bv.y;
    float o2 = (v.z - mu) * inv * gv.z + bv.z;
    float o3 = (v.w - mu) * inv * gv.w + bv.w;
    __half2 lo = __floats2half2_rn(o0, o1);
    __half2 hi = __floats2half2_rn(o2, o3);
    uint2 o;
    o.x = *reinterpret_cast<uint32_t*>(&lo);
    o.y = *reinterpret_cast<uint32_t*>(&hi);
    ((uint2*)(g_Ha + (size_t)row * Hn))[tid] = o;
}

// ---------------- launch (R9/R13 winning schedule) ----------------
extern "C" void kernel_launch(void* const* d_in, const int* in_sizes, int n_in,
                              void* d_out, int out_size) {
    const float* X     = (const float*)d_in[0];
    const void*  pos   = d_in[1];
    const float* W1    = (const float*)d_in[2];
    const float* b1    = (const float*)d_in[3];
    const float* gamma = (const float*)d_in[4];
    const float* beta  = (const float*)d_in[5];
    const float* W2    = (const float*)d_in[6];
    const float* b2    = (const float*)d_in[7];
    float* out = (float*)d_out;

    cudaFuncSetAttribute(gemm_f16_kernel, cudaFuncAttributeMaxDynamicSharedMemorySize, SMEM_TOTAL);

    void *pW1h, *pW2h, *pXg, *pHb, *pHa;
    cudaGetSymbolAddress(&pW1h, g_W1h);
    cudaGetSymbolAddress(&pW2h, g_W2h);
    cudaGetSymbolAddress(&pXg, g_Xg);
    cudaGetSymbolAddress(&pHb, g_Hb);
    cudaGetSymbolAddress(&pHa, g_Ha);
    const __half* Xg = (const __half*)pXg;
    float* Hb = (float*)pHb;
    const __half* Ha = (const __half*)pHa;

    static cudaStream_t sW = nullptr, sW1 = nullptr, sFE = nullptr;
    static cudaEvent_t eFork = nullptr, eJoin = nullptr, eJoin1 = nullptr,
                       eG = nullptr, eC1 = nullptr;
    if (!sW) {
        cudaStreamCreateWithFlags(&sW, cudaStreamNonBlocking);
        cudaStreamCreateWithFlags(&sW1, cudaStreamNonBlocking);
        cudaStreamCreateWithFlags(&sFE, cudaStreamNonBlocking);
        cudaEventCreateWithFlags(&eFork, cudaEventDisableTiming);
        cudaEventCreateWithFlags(&eJoin, cudaEventDisableTiming);
        cudaEventCreateWithFlags(&eJoin1, cudaEventDisableTiming);
        cudaEventCreateWithFlags(&eG, cudaEventDisableTiming);
        cudaEventCreateWithFlags(&eC1, cudaEventDisableTiming);
    }

    // Fork: weight converts overlap with the front-end.
    // W2: n4 = 1024*32000/4 = 8,192,000 = 1000 blocks * 1024/iter * 8 iters (exact)
    // W1: n4 = 1024*1024/4 = 262,144 = 256 blocks * 1024/iter * 1 iter (exact)
    cudaEventRecord(eFork, 0);
    cudaStreamWaitEvent(sW, eFork, 0);
    convert_kernel<<<1000, 256, 0, sW>>>((const float4*)W2, (uint2*)pW2h, Kdim * Vn / 4);
    cudaEventRecord(eJoin, sW);
    cudaStreamWaitEvent(sW1, eFork, 0);
    convert_kernel<<<256, 256, 0, sW1>>>((const float4*)W1, (uint2*)pW1h, Kdim * Hn / 4);
    cudaEventRecord(eJoin1, sW1);

    // Main stream: gather (width probe fused).
    gather_kernel<<<Mrows / 4, 256>>>(X, pos);
    cudaEventRecord(eG, 0);

    // ---- chunk c0 front-end (rows [0, MC0)) on main ----
    cudaStreamWaitEvent(0, eJoin1, 0);
    gemm_f16_kernel<<<dim3(MC0 / MT, Hn / NT), 256, SMEM_TOTAL>>>(
        Xg, (const __half*)pW1h, b1, Hb, (long long)Hn, (long long)Hn, 1);
    ln_kernel<<<MC0, 256>>>(gamma, beta, 0);

    // ---- chunk c1 front-end + GEMM2(c1) on sFE (independent of GEMM2(c0)) ----
    cudaStreamWaitEvent(sFE, eG, 0);
    cudaStreamWaitEvent(sFE, eJoin1, 0);
    gemm_f16_kernel<<<dim3(MC1 / MT, Hn / NT), 256, SMEM_TOTAL, sFE>>>(
        Xg + (size_t)MC0 * Kdim, (const __half*)pW1h, b1, Hb + (size_t)MC0 * Hn,
        (long long)Hn, (long long)Hn, 1);
    ln_kernel<<<MC1, 256, 0, sFE>>>(gamma, beta, MC0);
    cudaStreamWaitEvent(sFE, eJoin, 0);
    gemm_f16_kernel<<<dim3(MC1 / MT, Vn / NT), 256, SMEM_TOTAL, sFE>>>(
        Ha + (size_t)MC0 * Kdim, (const __half*)pW2h, b2, out + (size_t)MC0 * Vn,
        (long long)Vn, (long long)Vn, 0);
    cudaEventRecord(eC1, sFE);

    // ---- GEMM2(c0) on main, concurrent with GEMM2(c1) ----
    cudaStreamWaitEvent(0, eJoin, 0);
    gemm_f16_kernel<<<dim3(MC0 / MT, Vn / NT), 256, SMEM_TOTAL>>>(
        Ha, (const __half*)pW2h, b2, out, (long long)Vn, (long long)Vn, 0);

    // join the side branch back into the capture-origin stream
    cudaStreamWaitEvent(0, eC1, 0);
}